// round 4
// baseline (speedup 1.0000x reference)
#include <cuda_runtime.h>
#include <math.h>

// Problem constants
#define BATCH 4
#define T     2048
#define D     1024
#define MT    (BATCH * T)   // 8192 rows for QKV projection

// GEMM tiling: 128x128 CTA tile, BK=8, 256 threads, 8x8 micro-tile
#define BM 128
#define BN 128
#define BK 8
#define NTHREADS 256

// Device scratch (allocations are forbidden in kernel_launch)
__device__ float g_Q[MT * D];        // 32 MB
__device__ float g_K[MT * D];        // 32 MB
__device__ float g_V[MT * D];        // 32 MB
__device__ float g_S[BATCH * T * T]; // 64 MB scores -> softmax weights in place

// ---------------------------------------------------------------------------
// Shared GEMM body pieces (macro-free, inlined by hand in each kernel).
// Thread map: tx = tid & 15 (col group), ty = tid >> 4 (row group), 8x8 acc.
// A-tile loads: thread (tid>>1) = row 0..127, (tid&1)*4 = k offset; stored
// transposed As[k][row]. B-tile loads: row-major float4.
// ---------------------------------------------------------------------------

// Kernel 1: fused QKV projection. C = E @ W, W row-major [in,out].
// grid = (D/BN, MT/BM, 3)
__global__ __launch_bounds__(NTHREADS)
void qkv_kernel(const float* __restrict__ E,
                const float* __restrict__ Wk,
                const float* __restrict__ Wq,
                const float* __restrict__ Wv)
{
    const float* W;
    float* C;
    if (blockIdx.z == 0)      { W = Wk; C = g_K; }
    else if (blockIdx.z == 1) { W = Wq; C = g_Q; }
    else                      { W = Wv; C = g_V; }

    __shared__ float As[BK][BM];
    __shared__ float Bs[BK][BN];

    const int tid = threadIdx.x;
    const int tx = tid & 15;
    const int ty = tid >> 4;

    const int rowBase = blockIdx.y * BM;
    const int colBase = blockIdx.x * BN;

    const int aRow = tid >> 1;           // 0..127
    const int aCol = (tid & 1) << 2;     // 0 or 4
    const int bRow = tid >> 5;           // 0..7
    const int bCol = (tid & 31) << 2;    // 0..124

    const float* Aptr = E + (rowBase + aRow) * D + aCol;
    const float* Bptr = W + bRow * D + colBase + bCol;

    float acc[8][8] = {};

    for (int k0 = 0; k0 < D; k0 += BK) {
        float4 a = *(const float4*)(Aptr + k0);
        As[aCol + 0][aRow] = a.x;
        As[aCol + 1][aRow] = a.y;
        As[aCol + 2][aRow] = a.z;
        As[aCol + 3][aRow] = a.w;
        *(float4*)&Bs[bRow][bCol] = *(const float4*)(Bptr + k0 * D);
        __syncthreads();

        #pragma unroll
        for (int k = 0; k < BK; k++) {
            float4 a0 = *(const float4*)&As[k][ty * 8];
            float4 a1 = *(const float4*)&As[k][ty * 8 + 4];
            float4 b0 = *(const float4*)&Bs[k][tx * 8];
            float4 b1 = *(const float4*)&Bs[k][tx * 8 + 4];
            float ar[8] = {a0.x,a0.y,a0.z,a0.w,a1.x,a1.y,a1.z,a1.w};
            float br[8] = {b0.x,b0.y,b0.z,b0.w,b1.x,b1.y,b1.z,b1.w};
            #pragma unroll
            for (int i = 0; i < 8; i++)
                #pragma unroll
                for (int j = 0; j < 8; j++)
                    acc[i][j] = fmaf(ar[i], br[j], acc[i][j]);
        }
        __syncthreads();
    }

    #pragma unroll
    for (int i = 0; i < 8; i++) {
        float* out = C + (rowBase + ty * 8 + i) * D + colBase + tx * 8;
        *(float4*)out       = make_float4(acc[i][0], acc[i][1], acc[i][2], acc[i][3]);
        *(float4*)(out + 4) = make_float4(acc[i][4], acc[i][5], acc[i][6], acc[i][7]);
    }
}

// ---------------------------------------------------------------------------
// Kernel 2: causal scores. S[b] = (Q[b] @ K[b]^T) / 32, -inf above diagonal.
// Only lower-triangular tiles (jt <= it). grid = (T/BN, T/BM, BATCH)
// ---------------------------------------------------------------------------
__global__ __launch_bounds__(NTHREADS)
void scores_kernel()
{
    const int jt = blockIdx.x;
    const int it = blockIdx.y;
    if (jt > it) return;
    const int b = blockIdx.z;

    const float* Q  = g_Q + b * T * D;
    const float* Km = g_K + b * T * D;
    float* S = g_S + b * T * T;

    __shared__ float As[BK][BM];
    __shared__ float Bs[BK][BN];

    const int tid = threadIdx.x;
    const int tx = tid & 15;
    const int ty = tid >> 4;

    const int aRow = tid >> 1;
    const int aCol = (tid & 1) << 2;

    const float* Aptr = Q  + (it * BM + aRow) * D + aCol;
    const float* Bptr = Km + (jt * BN + aRow) * D + aCol;  // NT: K rows = out cols

    float acc[8][8] = {};

    for (int k0 = 0; k0 < D; k0 += BK) {
        float4 a = *(const float4*)(Aptr + k0);
        As[aCol + 0][aRow] = a.x;
        As[aCol + 1][aRow] = a.y;
        As[aCol + 2][aRow] = a.z;
        As[aCol + 3][aRow] = a.w;
        float4 bb = *(const float4*)(Bptr + k0);
        Bs[aCol + 0][aRow] = bb.x;
        Bs[aCol + 1][aRow] = bb.y;
        Bs[aCol + 2][aRow] = bb.z;
        Bs[aCol + 3][aRow] = bb.w;
        __syncthreads();

        #pragma unroll
        for (int k = 0; k < BK; k++) {
            float4 a0 = *(const float4*)&As[k][ty * 8];
            float4 a1 = *(const float4*)&As[k][ty * 8 + 4];
            float4 b0 = *(const float4*)&Bs[k][tx * 8];
            float4 b1 = *(const float4*)&Bs[k][tx * 8 + 4];
            float ar[8] = {a0.x,a0.y,a0.z,a0.w,a1.x,a1.y,a1.z,a1.w};
            float br[8] = {b0.x,b0.y,b0.z,b0.w,b1.x,b1.y,b1.z,b1.w};
            #pragma unroll
            for (int i = 0; i < 8; i++)
                #pragma unroll
                for (int j = 0; j < 8; j++)
                    acc[i][j] = fmaf(ar[i], br[j], acc[i][j]);
        }
        __syncthreads();
    }

    const float scale = 0.03125f;  // 1/sqrt(1024)
    #pragma unroll
    for (int i = 0; i < 8; i++) {
        const int grow = it * BM + ty * 8 + i;
        float* out = S + grow * T + jt * BN + tx * 8;
        #pragma unroll
        for (int j = 0; j < 8; j++) {
            const int gcol = jt * BN + tx * 8 + j;
            float v = acc[i][j] * scale;
            if (gcol > grow) v = -INFINITY;
            out[j] = v;
        }
    }
}

// ---------------------------------------------------------------------------
// Kernel 3: in-place row softmax over S. Row t covers cols [0, L) with L =
// ceil((t+1)/128)*128 (diagonal tile holds -inf above diag -> exp gives 0).
// grid = (BATCH*T)
// ---------------------------------------------------------------------------
__global__ __launch_bounds__(NTHREADS)
void softmax_kernel()
{
    const int r = blockIdx.x;
    const int b = r / T;
    const int t = r % T;
    float* row = g_S + b * T * T + t * T;
    const int L = ((t >> 7) + 1) << 7;   // ceil to 128 (= BN)

    __shared__ float red[NTHREADS];
    const int tid = threadIdx.x;

    float m = -INFINITY;
    for (int j = tid; j < L; j += NTHREADS) m = fmaxf(m, row[j]);
    red[tid] = m;
    __syncthreads();
    #pragma unroll
    for (int s = NTHREADS / 2; s > 0; s >>= 1) {
        if (tid < s) red[tid] = fmaxf(red[tid], red[tid + s]);
        __syncthreads();
    }
    m = red[0];
    __syncthreads();

    float sum = 0.0f;
    for (int j = tid; j < L; j += NTHREADS) {
        float e = __expf(row[j] - m);    // exp(-inf) = 0 handles the mask
        row[j] = e;
        sum += e;
    }
    red[tid] = sum;
    __syncthreads();
    #pragma unroll
    for (int s = NTHREADS / 2; s > 0; s >>= 1) {
        if (tid < s) red[tid] += red[tid + s];
        __syncthreads();
    }
    const float inv = 1.0f / red[0];
    __syncthreads();

    for (int j = tid; j < L; j += NTHREADS) row[j] *= inv;
}

// ---------------------------------------------------------------------------
// Kernel 4: O[b] = W[b] @ V[b] with causal k-bound; reference rounding.
// grid = (D/BN, T/BM, BATCH)
// ---------------------------------------------------------------------------
__global__ __launch_bounds__(NTHREADS)
void av_kernel(float* __restrict__ O)
{
    const int b  = blockIdx.z;
    const int it = blockIdx.y;

    const float* Wm = g_S + b * T * T;
    const float* V  = g_V + b * T * D;
    float* Out = O + b * T * D;

    __shared__ float As[BK][BM];
    __shared__ float Bs[BK][BN];

    const int tid = threadIdx.x;
    const int tx = tid & 15;
    const int ty = tid >> 4;

    const int rowBase = it * BM;
    const int colBase = blockIdx.x * BN;

    const int aRow = tid >> 1;
    const int aCol = (tid & 1) << 2;
    const int bRow = tid >> 5;
    const int bCol = (tid & 31) << 2;

    const float* Aptr = Wm + (rowBase + aRow) * T + aCol;
    const float* Bptr = V + bRow * D + colBase + bCol;

    float acc[8][8] = {};

    const int kMax = (it + 1) * BM;  // causal: keys <= last row of this tile

    for (int k0 = 0; k0 < kMax; k0 += BK) {
        float4 a = *(const float4*)(Aptr + k0);
        As[aCol + 0][aRow] = a.x;
        As[aCol + 1][aRow] = a.y;
        As[aCol + 2][aRow] = a.z;
        As[aCol + 3][aRow] = a.w;
        *(float4*)&Bs[bRow][bCol] = *(const float4*)(Bptr + k0 * D);
        __syncthreads();

        #pragma unroll
        for (int k = 0; k < BK; k++) {
            float4 a0 = *(const float4*)&As[k][ty * 8];
            float4 a1 = *(const float4*)&As[k][ty * 8 + 4];
            float4 b0 = *(const float4*)&Bs[k][tx * 8];
            float4 b1 = *(const float4*)&Bs[k][tx * 8 + 4];
            float ar[8] = {a0.x,a0.y,a0.z,a0.w,a1.x,a1.y,a1.z,a1.w};
            float br[8] = {b0.x,b0.y,b0.z,b0.w,b1.x,b1.y,b1.z,b1.w};
            #pragma unroll
            for (int i = 0; i < 8; i++)
                #pragma unroll
                for (int j = 0; j < 8; j++)
                    acc[i][j] = fmaf(ar[i], br[j], acc[i][j]);
        }
        __syncthreads();
    }

    #pragma unroll
    for (int i = 0; i < 8; i++) {
        float* out = Out + (rowBase + ty * 8 + i) * D + colBase + tx * 8;
        #pragma unroll
        for (int j = 0; j < 8; j++) {
            float v = acc[i][j];
            out[j] = rintf(v * 10000.0f) * 1.0e-4f;  // match reference round
        }
    }
}

// ---------------------------------------------------------------------------
extern "C" void kernel_launch(void* const* d_in, const int* in_sizes, int n_in,
                              void* d_out, int out_size)
{
    const float* E  = (const float*)d_in[0];  // embedded [4,2048,1024]
    const float* Wk = (const float*)d_in[1];
    const float* Wq = (const float*)d_in[2];
    const float* Wv = (const float*)d_in[3];
    float* O = (float*)d_out;

    dim3 blk(NTHREADS);
    qkv_kernel<<<dim3(D / BN, MT / BM, 3), blk>>>(E, Wk, Wq, Wv);
    scores_kernel<<<dim3(T / BN, T / BM, BATCH), blk>>>();
    softmax_kernel<<<dim3(BATCH * T), blk>>>();
    av_kernel<<<dim3(D / BN, T / BM, BATCH), blk>>>(O);
}

// round 6
// speedup vs baseline: 2.2088x; 2.2088x over previous
#include <cuda_runtime.h>
#include <cuda_bf16.h>
#include <stdint.h>
#include <stddef.h>
#include <math.h>

#define BATCH 4
#define T     2048
#define D     1024
#define MT    (BATCH * T)   // 8192
#define KE3   3072          // 3*D split-extended K (qkv, scores)

// CTA tile 128x128, 8 warps (2M x 4N), warp tile 64x32, BK=32
#define TM 128
#define TN 128
#define BK 32
#define ASTR 40     // 32 + 8 pad (elems) -> 80B rows, conflict-free ldmatrix
#define B2STR 136   // 128 + 8 pad (elems) for [k][n] V tiles

// ------------------------- device scratch ---------------------------------
__device__ __nv_bfloat16 g_Eext[(size_t)MT * KE3];          // A-role [hi|lo|hi]
__device__ __nv_bfloat16 g_WText[(size_t)3 * D * KE3];      // [n][k] B-role [hi|hi|lo]
__device__ __nv_bfloat16 g_Qext[(size_t)MT * KE3];          // A-role [hi|lo|hi]
__device__ __nv_bfloat16 g_Kext[(size_t)MT * KE3];          // B-role [hi|hi|lo]
__device__ __nv_bfloat16 g_Vext[(size_t)BATCH * 3 * T * D]; // [b][seg][t][d], seg=[hi,hi,lo]
__device__ float         g_S[(size_t)BATCH * T * T];        // fp32 scores
__device__ __nv_bfloat16 g_Sext[(size_t)BATCH * T * 3 * T]; // A-role [hi|lo|hi] along keys

// ------------------------- helpers ------------------------------------
__device__ __forceinline__ uint32_t smem_u32(const void* p) {
    uint32_t a;
    asm("{ .reg .u64 t; cvta.to.shared.u64 t, %1; cvt.u32.u64 %0, t; }" : "=r"(a) : "l"(p));
    return a;
}
__device__ __forceinline__ void ldsm_x4(uint32_t& r0, uint32_t& r1, uint32_t& r2, uint32_t& r3,
                                        uint32_t addr) {
    asm volatile("ldmatrix.sync.aligned.m8n8.x4.shared.b16 {%0,%1,%2,%3}, [%4];"
                 : "=r"(r0), "=r"(r1), "=r"(r2), "=r"(r3) : "r"(addr));
}
__device__ __forceinline__ void ldsm_x4_t(uint32_t& r0, uint32_t& r1, uint32_t& r2, uint32_t& r3,
                                          uint32_t addr) {
    asm volatile("ldmatrix.sync.aligned.m8n8.x4.trans.shared.b16 {%0,%1,%2,%3}, [%4];"
                 : "=r"(r0), "=r"(r1), "=r"(r2), "=r"(r3) : "r"(addr));
}
__device__ __forceinline__ void mma_bf16(float* c, const uint32_t* a, const uint32_t* b) {
    asm volatile("mma.sync.aligned.m16n8k16.row.col.f32.bf16.bf16.f32 "
                 "{%0,%1,%2,%3}, {%4,%5,%6,%7}, {%8,%9}, {%0,%1,%2,%3};"
                 : "+f"(c[0]), "+f"(c[1]), "+f"(c[2]), "+f"(c[3])
                 : "r"(a[0]), "r"(a[1]), "r"(a[2]), "r"(a[3]), "r"(b[0]), "r"(b[1]));
}
__device__ __forceinline__ void bsplit(float x, __nv_bfloat16& h, __nv_bfloat16& l) {
    h = __float2bfloat16(x);
    l = __float2bfloat16(x - __bfloat162float(h));
}
__device__ __forceinline__ __nv_bfloat162 mk2(__nv_bfloat16 a, __nv_bfloat16 b) {
    __nv_bfloat162 v; v.x = a; v.y = b; return v;
}

// ------------------------- conversion kernels ------------------------------
__global__ __launch_bounds__(256)
void convE_kernel(const float* __restrict__ E) {
    int idx = blockIdx.x * 256 + threadIdx.x;   // over MT*D
    int row = idx >> 10, k = idx & 1023;
    __nv_bfloat16 h, l;
    bsplit(E[idx], h, l);
    __nv_bfloat16* p = g_Eext + (size_t)row * KE3;
    p[k] = h; p[D + k] = l; p[2 * D + k] = h;   // A-role [hi, lo, hi]
}

__global__ __launch_bounds__(256)
void convW_kernel(const float* __restrict__ Wk, const float* __restrict__ Wq,
                  const float* __restrict__ Wv) {
    const float* W = (blockIdx.z == 0) ? Wk : (blockIdx.z == 1) ? Wq : Wv;
    __nv_bfloat16* dst = g_WText + (size_t)blockIdx.z * D * KE3;
    __shared__ float tsm[32][33];
    int n0 = blockIdx.x * 32, k0 = blockIdx.y * 32;
    int tx = threadIdx.x, ty = threadIdx.y;
    #pragma unroll
    for (int i = 0; i < 4; i++)
        tsm[ty + 8 * i][tx] = W[(size_t)(k0 + ty + 8 * i) * D + n0 + tx];
    __syncthreads();
    #pragma unroll
    for (int i = 0; i < 4; i++) {
        int n = n0 + ty + 8 * i, k = k0 + tx;
        __nv_bfloat16 h, l;
        bsplit(tsm[tx][ty + 8 * i], h, l);       // = W[k][n]
        __nv_bfloat16* p = dst + (size_t)n * KE3;
        p[k] = h; p[D + k] = h; p[2 * D + k] = l;  // B-role [hi, hi, lo]
    }
}

// ------------------------- unified mma.sync GEMM ---------------------------
// MODE 0: qkv   out = E_ext @ WText[z]^T       grid (8, 64, 3)
// MODE 1: score S[b] = Q_ext @ K_ext^T (/32, causal)  grid (16, 16, 4)
// MODE 2: av    O[b] = S_ext @ V_ext (trans-B, k-bounded, rounded)  grid (8, 16, 4)
template <int MODE>
__global__ __launch_bounds__(256)
void gemm_mma(float* __restrict__ outp) {
    __shared__ __nv_bfloat16 As[TM * ASTR];   // 10240 B
    __shared__ __nv_bfloat16 Bs[TM * ASTR];   // 10240 B (mode2 uses 32*136 <= this)

    const int tid = threadIdx.x;
    const int wid = tid >> 5, l = tid & 31;
    const int wm = wid & 1, wn = wid >> 1;          // 2 x 4 warp grid
    const int warpM = wm * 64, warpN = wn * 32;
    const int bx = blockIdx.x, by = blockIdx.y, bz = blockIdx.z;
    const int mBase = by * TM, nBase = bx * TN;

    const __nv_bfloat16 *Ag, *Bg;
    int ldk;           // A row stride (and mode0/1 B row stride)
    int nIter, nJ;
    if (MODE == 0) {
        Ag = g_Eext; Bg = g_WText + (size_t)bz * D * KE3;
        ldk = KE3; nJ = KE3 / BK; nIter = nJ;
    } else if (MODE == 1) {
        if (bx > by) return;                        // strictly above diagonal
        Ag = g_Qext + (size_t)bz * T * KE3;
        Bg = g_Kext + (size_t)bz * T * KE3;
        ldk = KE3; nJ = KE3 / BK; nIter = nJ;
    } else {
        Ag = g_Sext + (size_t)bz * T * (3 * T);
        Bg = g_Vext + (size_t)bz * (3 * T) * D;
        ldk = 3 * T;
        nJ = ((by + 1) * TM) / BK;                  // causal K bound per segment
        nIter = 3 * nJ;
    }

    float c[4][4][4] = {};
    uint4 pa[2], pb[2];

    // ---- loaders (into registers) ----
    const int aRow = tid >> 2;                 // 0..63 (+64 second group)
    const int aKc  = (tid & 3) * 8;            // 0,8,16,24
    const int vRow = tid >> 4;                 // 0..15 (+16 second group)
    const int vNc  = (tid & 15) * 8;           // 0..120

    auto kOff = [&](int it) -> int {
        if (MODE == 2) { int s = it / nJ; return s * T + (it - s * nJ) * BK; }
        return it * BK;
    };
    auto loadG = [&](int ko) {
        pa[0] = *(const uint4*)(Ag + (size_t)(mBase + aRow) * ldk + ko + aKc);
        pa[1] = *(const uint4*)(Ag + (size_t)(mBase + aRow + 64) * ldk + ko + aKc);
        if (MODE != 2) {
            pb[0] = *(const uint4*)(Bg + (size_t)(nBase + aRow) * ldk + ko + aKc);
            pb[1] = *(const uint4*)(Bg + (size_t)(nBase + aRow + 64) * ldk + ko + aKc);
        } else {
            pb[0] = *(const uint4*)(Bg + (size_t)(ko + vRow) * D + nBase + vNc);
            pb[1] = *(const uint4*)(Bg + (size_t)(ko + vRow + 16) * D + nBase + vNc);
        }
    };
    auto stsAll = [&]() {
        *(uint4*)&As[aRow * ASTR + aKc]        = pa[0];
        *(uint4*)&As[(aRow + 64) * ASTR + aKc] = pa[1];
        if (MODE != 2) {
            *(uint4*)&Bs[aRow * ASTR + aKc]        = pb[0];
            *(uint4*)&Bs[(aRow + 64) * ASTR + aKc] = pb[1];
        } else {
            *(uint4*)&Bs[vRow * B2STR + vNc]        = pb[0];
            *(uint4*)&Bs[(vRow + 16) * B2STR + vNc] = pb[1];
        }
    };

    const uint32_t AsU = smem_u32(As), BsU = smem_u32(Bs);
    // lane-invariant pieces of ldmatrix addressing
    const int aLR = (l & 15), aLC = (l >> 4) * 8;            // A: row sel, k sel
    const int bLR = (l >> 4) * 8 + (l & 7), bLC = ((l >> 3) & 1) * 8;  // B[n][k]
    const int vLR = ((l >> 3) & 1) * 8 + (l & 7), vLC = (l >> 4) * 8;  // B[k][n] trans

    loadG(kOff(0));

    for (int it = 0; it < nIter; it++) {
        stsAll();
        __syncthreads();
        if (it + 1 < nIter) loadG(kOff(it + 1));

        #pragma unroll
        for (int ks = 0; ks < 2; ks++) {
            uint32_t a[4][4], b[4][2];
            #pragma unroll
            for (int mi = 0; mi < 4; mi++)
                ldsm_x4(a[mi][0], a[mi][1], a[mi][2], a[mi][3],
                        AsU + ((warpM + mi * 16 + aLR) * ASTR + ks * 16 + aLC) * 2);
            if (MODE != 2) {
                #pragma unroll
                for (int n2 = 0; n2 < 4; n2 += 2)
                    ldsm_x4(b[n2][0], b[n2][1], b[n2 + 1][0], b[n2 + 1][1],
                            BsU + ((warpN + n2 * 8 + bLR) * ASTR + ks * 16 + bLC) * 2);
            } else {
                #pragma unroll
                for (int n2 = 0; n2 < 4; n2 += 2)
                    ldsm_x4_t(b[n2][0], b[n2][1], b[n2 + 1][0], b[n2 + 1][1],
                              BsU + ((ks * 16 + vLR) * B2STR + warpN + n2 * 8 + vLC) * 2);
            }
            #pragma unroll
            for (int mi = 0; mi < 4; mi++)
                #pragma unroll
                for (int ni = 0; ni < 4; ni++)
                    mma_bf16(c[mi][ni], a[mi], b[ni]);
        }
        __syncthreads();
    }

    // ---- epilogue (direct from accumulators) ----
    const int l4 = l >> 2, l2 = (l & 3) * 2;
    #pragma unroll
    for (int mi = 0; mi < 4; mi++) {
        #pragma unroll
        for (int ni = 0; ni < 4; ni++) {
            const int n = nBase + warpN + ni * 8 + l2;
            #pragma unroll
            for (int half = 0; half < 2; half++) {
                const int m = mBase + warpM + mi * 16 + l4 + half * 8;
                float v0 = c[mi][ni][half * 2 + 0];
                float v1 = c[mi][ni][half * 2 + 1];
                if (MODE == 0) {
                    __nv_bfloat16 h0, l0, h1, l1;
                    bsplit(v0, h0, l0); bsplit(v1, h1, l1);
                    if (bz == 1) {        // Q: A-role [hi, lo, hi]
                        __nv_bfloat16* p = g_Qext + (size_t)m * KE3;
                        *(__nv_bfloat162*)(p + n)         = mk2(h0, h1);
                        *(__nv_bfloat162*)(p + D + n)     = mk2(l0, l1);
                        *(__nv_bfloat162*)(p + 2 * D + n) = mk2(h0, h1);
                    } else if (bz == 0) { // K: B-role [hi, hi, lo]
                        __nv_bfloat16* p = g_Kext + (size_t)m * KE3;
                        *(__nv_bfloat162*)(p + n)         = mk2(h0, h1);
                        *(__nv_bfloat162*)(p + D + n)     = mk2(h0, h1);
                        *(__nv_bfloat162*)(p + 2 * D + n) = mk2(l0, l1);
                    } else {              // V: [b][seg][t][d], segs [hi, hi, lo]
                        int bb = m >> 11, t = m & (T - 1);
                        __nv_bfloat16* p = g_Vext + (size_t)bb * 3 * T * D;
                        *(__nv_bfloat162*)(p + (size_t)t * D + n)           = mk2(h0, h1);
                        *(__nv_bfloat162*)(p + (size_t)(T + t) * D + n)     = mk2(h0, h1);
                        *(__nv_bfloat162*)(p + (size_t)(2 * T + t) * D + n) = mk2(l0, l1);
                    }
                } else if (MODE == 1) {
                    float s0 = (n     > m) ? -INFINITY : v0 * 0.03125f;
                    float s1 = (n + 1 > m) ? -INFINITY : v1 * 0.03125f;
                    float* p = g_S + (size_t)bz * T * T + (size_t)m * T + n;
                    p[0] = s0; p[1] = s1;
                } else {
                    float* p = outp + (size_t)bz * T * D + (size_t)m * D + n;
                    p[0] = rintf(v0 * 10000.0f) * 1.0e-4f;
                    p[1] = rintf(v1 * 10000.0f) * 1.0e-4f;
                }
            }
        }
    }
}

// ------------------------- softmax -> split bf16 ---------------------------
__global__ __launch_bounds__(256)
void softmax_kernel() {
    const int r = blockIdx.x;
    const int b = r >> 11, t = r & (T - 1);
    float* row = g_S + (size_t)b * T * T + (size_t)t * T;
    __nv_bfloat16* orow = g_Sext + ((size_t)b * T + t) * (3 * T);
    const int L = ((t >> 7) + 1) << 7;   // ceil to 128-tile

    __shared__ float red[256];
    const int tid = threadIdx.x;

    float m = -INFINITY;
    for (int j = tid; j < L; j += 256) m = fmaxf(m, row[j]);
    red[tid] = m;
    __syncthreads();
    #pragma unroll
    for (int s = 128; s > 0; s >>= 1) {
        if (tid < s) red[tid] = fmaxf(red[tid], red[tid + s]);
        __syncthreads();
    }
    m = red[0];
    __syncthreads();

    float sum = 0.0f;
    for (int j = tid; j < L; j += 256) {
        float e = __expf(row[j] - m);   // exp(-inf)=0 handles the causal mask
        row[j] = e;
        sum += e;
    }
    red[tid] = sum;
    __syncthreads();
    #pragma unroll
    for (int s = 128; s > 0; s >>= 1) {
        if (tid < s) red[tid] += red[tid + s];
        __syncthreads();
    }
    const float inv = 1.0f / red[0];
    __syncthreads();

    for (int j = tid; j < L; j += 256) {
        float w = row[j] * inv;
        __nv_bfloat16 h, l;
        bsplit(w, h, l);
        orow[j] = h; orow[T + j] = l; orow[2 * T + j] = h;   // A-role [hi, lo, hi]
    }
}

// ---------------------------------------------------------------------------
extern "C" void kernel_launch(void* const* d_in, const int* in_sizes, int n_in,
                              void* d_out, int out_size) {
    const float* E  = (const float*)d_in[0];
    const float* Wk = (const float*)d_in[1];
    const float* Wq = (const float*)d_in[2];
    const float* Wv = (const float*)d_in[3];
    float* O = (float*)d_out;

    convE_kernel<<<(MT * D) / 256, 256>>>(E);
    convW_kernel<<<dim3(32, 32, 3), dim3(32, 8)>>>(Wk, Wq, Wv);
    gemm_mma<0><<<dim3(D / TN, MT / TM, 3), 256>>>(O);
    gemm_mma<1><<<dim3(T / TN, T / TM, BATCH), 256>>>(O);
    softmax_kernel<<<MT, 256>>>();
    gemm_mma<2><<<dim3(D / TN, T / TM, BATCH), 256>>>(O);
}